// round 2
// baseline (speedup 1.0000x reference)
#include <cuda_runtime.h>
#include <math.h>

#define B_  4
#define T_  2048
#define D_  1024
#define H_  16
#define DH_ 64
#define M_  (B_*T_)      // 8192 rows
#define MAXREL 128

// ---------------- scratch (device globals; no allocs allowed) ----------------
__device__ float g_xn[M_*D_];
__device__ float g_q [M_*D_];
__device__ float g_k [M_*D_];
__device__ float g_v [M_*D_];
__device__ float g_y [M_*D_];

// ---------------- LayerNorm: one block per row ----------------
__global__ void ln_kernel(const float* __restrict__ x, const float* __restrict__ gamma,
                          const float* __restrict__ beta, float* __restrict__ out)
{
    const int row = blockIdx.x;
    const int tid = threadIdx.x;              // 256 threads, 4 floats each
    const float4 v = *(const float4*)(x + (size_t)row*D_ + tid*4);
    float s  = v.x + v.y + v.z + v.w;
    float ss = v.x*v.x + v.y*v.y + v.z*v.z + v.w*v.w;
    #pragma unroll
    for (int off = 16; off; off >>= 1) {
        s  += __shfl_xor_sync(0xffffffffu, s,  off);
        ss += __shfl_xor_sync(0xffffffffu, ss, off);
    }
    __shared__ float sh_s[8], sh_ss[8];
    const int w = tid >> 5;
    if ((tid & 31) == 0) { sh_s[w] = s; sh_ss[w] = ss; }
    __syncthreads();
    float ts = 0.f, tss = 0.f;
    #pragma unroll
    for (int i = 0; i < 8; i++) { ts += sh_s[i]; tss += sh_ss[i]; }
    const float mu   = ts * (1.0f / D_);
    const float var  = tss * (1.0f / D_) - mu * mu;
    const float rstd = rsqrtf(var + 1e-5f);
    const float4 gv = *(const float4*)(gamma + tid*4);
    const float4 bv = *(const float4*)(beta  + tid*4);
    float4 o;
    o.x = (v.x - mu) * rstd * gv.x + bv.x;
    o.y = (v.y - mu) * rstd * gv.y + bv.y;
    o.z = (v.z - mu) * rstd * gv.z + bv.z;
    o.w = (v.w - mu) * rstd * gv.w + bv.w;
    *(float4*)(out + (size_t)row*D_ + tid*4) = o;
}

// ---------------- SGEMM body: C[m][n] = scale * sum_k A[m][k]*B[n][k] (+res) -
// 128x128 tile, BK=8, 256 threads, 8x8 per thread.
template<bool RES>
__device__ __forceinline__ void sgemm_body(
    const float* __restrict__ A, const float* __restrict__ Bm,
    float* __restrict__ C, const float* __restrict__ res,
    float scale, int K, int N)
{
    __shared__ float As[8][132];
    __shared__ float Bs[8][132];
    const int tid = threadIdx.x;
    const int tx = tid & 15, ty = tid >> 4;
    const int m0 = blockIdx.y * 128, n0 = blockIdx.x * 128;
    const int lrow = tid >> 1, lh4 = (tid & 1) * 4;
    const float* Ag = A  + (size_t)(m0 + lrow) * K + lh4;
    const float* Bg = Bm + (size_t)(n0 + lrow) * K + lh4;

    float acc[8][8];
    #pragma unroll
    for (int i = 0; i < 8; i++)
        #pragma unroll
        for (int j = 0; j < 8; j++) acc[i][j] = 0.f;

    for (int k0 = 0; k0 < K; k0 += 8) {
        const float4 a4 = *(const float4*)(Ag + k0);
        const float4 b4 = *(const float4*)(Bg + k0);
        __syncthreads();
        As[lh4+0][lrow] = a4.x; As[lh4+1][lrow] = a4.y;
        As[lh4+2][lrow] = a4.z; As[lh4+3][lrow] = a4.w;
        Bs[lh4+0][lrow] = b4.x; Bs[lh4+1][lrow] = b4.y;
        Bs[lh4+2][lrow] = b4.z; Bs[lh4+3][lrow] = b4.w;
        __syncthreads();
        #pragma unroll
        for (int kk = 0; kk < 8; kk++) {
            float a[8], b[8];
            *(float4*)&a[0] = *(const float4*)&As[kk][ty*8];
            *(float4*)&a[4] = *(const float4*)&As[kk][ty*8+4];
            *(float4*)&b[0] = *(const float4*)&Bs[kk][tx*8];
            *(float4*)&b[4] = *(const float4*)&Bs[kk][tx*8+4];
            #pragma unroll
            for (int i = 0; i < 8; i++)
                #pragma unroll
                for (int j = 0; j < 8; j++)
                    acc[i][j] += a[i] * b[j];
        }
    }

    #pragma unroll
    for (int i = 0; i < 8; i++) {
        const int m = m0 + ty*8 + i;
        #pragma unroll
        for (int j = 0; j < 8; j += 4) {
            const int n = n0 + tx*8 + j;
            float4 o;
            o.x = acc[i][j+0] * scale;
            o.y = acc[i][j+1] * scale;
            o.z = acc[i][j+2] * scale;
            o.w = acc[i][j+3] * scale;
            if (RES) {
                const float4 rv = *(const float4*)(res + (size_t)m*N + n);
                o.x += rv.x; o.y += rv.y; o.z += rv.z; o.w += rv.w;
            }
            *(float4*)(C + (size_t)m*N + n) = o;
        }
    }
}

// QKV fused (blockIdx.z selects W); q scaled by 1/sqrt(DH)=0.125
__global__ void qkv_kernel(const float* __restrict__ xn,
                           const float* __restrict__ Wq, const float* __restrict__ Wk,
                           const float* __restrict__ Wv,
                           float* __restrict__ q, float* __restrict__ k, float* __restrict__ v)
{
    const float* W; float* C; float scale;
    if (blockIdx.z == 0)      { W = Wq; C = q; scale = 0.125f; }
    else if (blockIdx.z == 1) { W = Wk; C = k; scale = 1.0f; }
    else                      { W = Wv; C = v; scale = 1.0f; }
    sgemm_body<false>(xn, W, C, nullptr, scale, D_, D_);
}

__global__ void out_kernel(const float* __restrict__ y, const float* __restrict__ Wo,
                           const float* __restrict__ x, float* __restrict__ out)
{
    sgemm_body<true>(y, Wo, out, x, 1.0f, D_, D_);
}

// ---------------- Flash attention with causal mask + relative bias -----------
// Grid: (32 qblocks, 16 heads, 4 batch), 256 threads.
// Tiles 64x64, smem staged transposed for conflict-free float4 reads.
#define SROW 68   // padded row stride
__global__ void attn_kernel(const float* __restrict__ q, const float* __restrict__ k,
                            const float* __restrict__ v, const float* __restrict__ rel,
                            float* __restrict__ y)
{
    extern __shared__ float sm[];
    float* Qst   = sm;                  // [d][i] 64xSROW
    float* Kst   = sm + 64*SROW;        // [d][j]
    float* Pst   = sm + 2*64*SROW;      // [j][i]
    float* Vs    = sm + 3*64*SROW;      // [j][d]
    float* rel_s = sm + 4*64*SROW;      // 129

    const int qb = 31 - (int)blockIdx.x;   // heavy blocks first
    const int h  = blockIdx.y;
    const int b  = blockIdx.z;
    const int tid = threadIdx.x;
    const int tx = tid & 15, ty = tid >> 4;

    for (int i = tid; i <= MAXREL; i += 256) rel_s[i] = rel[h*(MAXREL+1) + i];

    // load Q tile transposed: Qst[d][i]
    const int qrow0 = b*T_ + qb*64;
    #pragma unroll
    for (int it = 0; it < 4; it++) {
        const int f4 = tid + it*256;
        const int r  = f4 >> 4;
        const int dq = (f4 & 15) * 4;
        const float4 val = *(const float4*)(q + (size_t)(qrow0 + r)*D_ + h*DH_ + dq);
        Qst[(dq+0)*SROW + r] = val.x;
        Qst[(dq+1)*SROW + r] = val.y;
        Qst[(dq+2)*SROW + r] = val.z;
        Qst[(dq+3)*SROW + r] = val.w;
    }

    float mreg[4], lreg[4], o[4][4];
    #pragma unroll
    for (int r = 0; r < 4; r++) {
        mreg[r] = -1e30f; lreg[r] = 0.f;
        #pragma unroll
        for (int c = 0; c < 4; c++) o[r][c] = 0.f;
    }

    for (int kb = 0; kb <= qb; kb++) {
        __syncthreads();   // protect Kst/Vs/Pst from previous iteration readers
        const int krow0 = b*T_ + kb*64;
        #pragma unroll
        for (int it = 0; it < 4; it++) {
            const int f4 = tid + it*256;
            const int r  = f4 >> 4;
            const int dq = (f4 & 15) * 4;
            const float4 kv = *(const float4*)(k + (size_t)(krow0 + r)*D_ + h*DH_ + dq);
            Kst[(dq+0)*SROW + r] = kv.x;
            Kst[(dq+1)*SROW + r] = kv.y;
            Kst[(dq+2)*SROW + r] = kv.z;
            Kst[(dq+3)*SROW + r] = kv.w;
            *(float4*)(Vs + (size_t)r*SROW + dq) =
                *(const float4*)(v + (size_t)(krow0 + r)*D_ + h*DH_ + dq);
        }
        __syncthreads();

        // S = Q K^T (64x64), 4x4 per thread
        float s[4][4];
        #pragma unroll
        for (int r = 0; r < 4; r++)
            #pragma unroll
            for (int c = 0; c < 4; c++) s[r][c] = 0.f;
        #pragma unroll 16
        for (int d = 0; d < 64; d++) {
            const float4 aq = *(const float4*)(Qst + d*SROW + ty*4);
            const float4 bk = *(const float4*)(Kst + d*SROW + tx*4);
            const float a[4] = {aq.x, aq.y, aq.z, aq.w};
            const float bb[4] = {bk.x, bk.y, bk.z, bk.w};
            #pragma unroll
            for (int r = 0; r < 4; r++)
                #pragma unroll
                for (int c = 0; c < 4; c++) s[r][c] += a[r] * bb[c];
        }

        // bias + causal mask
        const int ig0 = qb*64 + ty*4;
        const int jg0 = kb*64 + tx*4;
        #pragma unroll
        for (int r = 0; r < 4; r++)
            #pragma unroll
            for (int c = 0; c < 4; c++) {
                const int dist = (ig0 + r) - (jg0 + c);
                if (dist < 0) s[r][c] = -1e30f;
                else          s[r][c] += rel_s[dist > MAXREL ? MAXREL : dist];
            }

        // online softmax (rows spread across the 16 lanes sharing ty)
        float alpha[4];
        #pragma unroll
        for (int r = 0; r < 4; r++) {
            float mx = fmaxf(fmaxf(s[r][0], s[r][1]), fmaxf(s[r][2], s[r][3]));
            #pragma unroll
            for (int off = 8; off; off >>= 1)
                mx = fmaxf(mx, __shfl_xor_sync(0xffffffffu, mx, off));
            const float mnew = fmaxf(mreg[r], mx);
            alpha[r] = __expf(mreg[r] - mnew);
            float rsum = 0.f;
            #pragma unroll
            for (int c = 0; c < 4; c++) {
                const float p = __expf(s[r][c] - mnew);
                s[r][c] = p;
                rsum += p;
            }
            #pragma unroll
            for (int off = 8; off; off >>= 1)
                rsum += __shfl_xor_sync(0xffffffffu, rsum, off);
            lreg[r] = lreg[r] * alpha[r] + rsum;
            mreg[r] = mnew;
            #pragma unroll
            for (int c = 0; c < 4; c++) o[r][c] *= alpha[r];
        }

        // write P transposed: Pst[j][i] (contiguous in i)
        #pragma unroll
        for (int c = 0; c < 4; c++)
            *(float4*)(Pst + (tx*4+c)*SROW + ty*4) =
                make_float4(s[0][c], s[1][c], s[2][c], s[3][c]);
        __syncthreads();

        // O += P V
        #pragma unroll 16
        for (int j = 0; j < 64; j++) {
            const float4 pv = *(const float4*)(Pst + j*SROW + ty*4);
            const float4 vv = *(const float4*)(Vs  + j*SROW + tx*4);
            const float p[4] = {pv.x, pv.y, pv.z, pv.w};
            const float vb[4] = {vv.x, vv.y, vv.z, vv.w};
            #pragma unroll
            for (int r = 0; r < 4; r++)
                #pragma unroll
                for (int c = 0; c < 4; c++) o[r][c] += p[r] * vb[c];
        }
    }

    #pragma unroll
    for (int r = 0; r < 4; r++) {
        const float inv = 1.0f / lreg[r];
        const int ig = qb*64 + ty*4 + r;
        *(float4*)(y + (size_t)(b*T_ + ig)*D_ + h*DH_ + tx*4) =
            make_float4(o[r][0]*inv, o[r][1]*inv, o[r][2]*inv, o[r][3]*inv);
    }
}

#define ATTN_SMEM ((4*64*SROW + 132) * (int)sizeof(float))

extern "C" void kernel_launch(void* const* d_in, const int* in_sizes, int n_in,
                              void* d_out, int out_size)
{
    const float* x     = (const float*)d_in[0];
    const float* Wq    = (const float*)d_in[1];
    const float* Wk    = (const float*)d_in[2];
    const float* Wv    = (const float*)d_in[3];
    const float* Wo    = (const float*)d_in[4];
    const float* rel   = (const float*)d_in[5];
    const float* gamma = (const float*)d_in[6];
    const float* beta  = (const float*)d_in[7];
    float* out = (float*)d_out;

    float *p_xn, *p_q, *p_k, *p_v, *p_y;
    cudaGetSymbolAddress((void**)&p_xn, g_xn);
    cudaGetSymbolAddress((void**)&p_q,  g_q);
    cudaGetSymbolAddress((void**)&p_k,  g_k);
    cudaGetSymbolAddress((void**)&p_v,  g_v);
    cudaGetSymbolAddress((void**)&p_y,  g_y);

    cudaFuncSetAttribute(attn_kernel, cudaFuncAttributeMaxDynamicSharedMemorySize, ATTN_SMEM);

    ln_kernel<<<M_, 256>>>(x, gamma, beta, p_xn);
    qkv_kernel<<<dim3(D_/128, M_/128, 3), 256>>>(p_xn, Wq, Wk, Wv, p_q, p_k, p_v);
    attn_kernel<<<dim3(T_/64, H_, B_), 256, ATTN_SMEM>>>(p_q, p_k, p_v, rel, p_y);
    out_kernel<<<dim3(D_/128, M_/128), 256>>>(p_y, Wo, x, out);
}